// round 1
// baseline (speedup 1.0000x reference)
#include <cuda_runtime.h>
#include <cuda_fp16.h>
#include <cstdint>

// ---------------------------------------------------------------------------
// Problem constants
// ---------------------------------------------------------------------------
#define BATCH 32
#define HDIM  64
#define WDIM  64
#define CDIM  512
#define NHEAD 16
#define WINSZ 8
#define SHIFT 4
#define SEQ   64                   // tokens per window
#define HEADD 32
#define FFDIM 2048
#define MTOK  131072               // B * H * W

// ---------------------------------------------------------------------------
// Scratch (static __device__ arrays; allocation APIs are forbidden)
// ---------------------------------------------------------------------------
__device__ __half g_xw  [ (size_t)MTOK * CDIM  ];   // LN1+shift+partitioned, fp16
__device__ __half g_qkv [ (size_t)MTOK * 3*CDIM];   // qkv in window order
__device__ __half g_attn[ (size_t)MTOK * CDIM  ];   // attention out, window order
__device__ float  g_proj[ (size_t)MTOK * CDIM  ];   // out-proj, window order, fp32
__device__ float  g_x   [ (size_t)MTOK * CDIM  ];   // residual (natural order), fp32
__device__ __half g_h   [ (size_t)MTOK * CDIM  ];   // LN2 output, fp16
__device__ __half g_ff  [ (size_t)MTOK * FFDIM ];   // MLP hidden, fp16
__device__ __half g_wqkvT[3*CDIM * CDIM];           // [1536][512]
__device__ __half g_woT  [CDIM * CDIM];             // [512][512]
__device__ __half g_w1T  [FFDIM * CDIM];            // [2048][512]
__device__ __half g_w2T  [CDIM * FFDIM];            // [512][2048]

// ---------------------------------------------------------------------------
// Small helpers
// ---------------------------------------------------------------------------
__device__ __forceinline__ void cp16(void* smem, const void* gmem) {
    unsigned s = (unsigned)__cvta_generic_to_shared(smem);
    asm volatile("cp.async.cg.shared.global [%0], [%1], 16;\n" :: "r"(s), "l"(gmem));
}
__device__ __forceinline__ void cp_commit() { asm volatile("cp.async.commit_group;\n"); }
__device__ __forceinline__ void cp_wait0()  { asm volatile("cp.async.wait_group 0;\n"); }

__device__ __forceinline__ void ldm4(uint32_t& r0, uint32_t& r1, uint32_t& r2, uint32_t& r3,
                                     const __half* p) {
    unsigned s = (unsigned)__cvta_generic_to_shared(p);
    asm volatile("ldmatrix.sync.aligned.m8n8.x4.shared.b16 {%0,%1,%2,%3},[%4];\n"
                 : "=r"(r0), "=r"(r1), "=r"(r2), "=r"(r3) : "r"(s));
}
__device__ __forceinline__ void mma16816(float& c0, float& c1, float& c2, float& c3,
                                         uint32_t a0, uint32_t a1, uint32_t a2, uint32_t a3,
                                         uint32_t b0, uint32_t b1) {
    asm volatile("mma.sync.aligned.m16n8k16.row.col.f32.f16.f16.f32 "
                 "{%0,%1,%2,%3},{%4,%5,%6,%7},{%8,%9},{%0,%1,%2,%3};\n"
                 : "+f"(c0), "+f"(c1), "+f"(c2), "+f"(c3)
                 : "r"(a0), "r"(a1), "r"(a2), "r"(a3), "r"(b0), "r"(b1));
}
__device__ __forceinline__ float gelu_tanh(float x) {
    float x3 = x * x * x;
    return 0.5f * x * (1.0f + tanhf(0.7978845608028654f * (x + 0.044715f * x3)));
}

// ---------------------------------------------------------------------------
// Weight transpose + fp32->fp16 convert: W[K][N] -> Wt[N][K]
// ---------------------------------------------------------------------------
__global__ void k_transpose(const float* __restrict__ W, __half* __restrict__ Wt,
                            int K, int N) {
    int i = blockIdx.x * 256 + threadIdx.x;
    if (i >= K * N) return;
    int n = i / K;
    int k = i - n * K;
    Wt[i] = __float2half(W[(size_t)k * N + n]);
}

// ---------------------------------------------------------------------------
// Kernel 1: LN1 + roll(-4,-4) + window partition. One block per output row.
// ---------------------------------------------------------------------------
__global__ __launch_bounds__(128) void k_ln1(const float* __restrict__ hs,
                                             const float* __restrict__ g,
                                             const float* __restrict__ b,
                                             __half* __restrict__ xw) {
    int n    = blockIdx.x;
    int bimg = n >> 12;
    int rem  = n & 4095;
    int wid  = rem >> 6, t = rem & 63;
    int wy = wid >> 3, wx = wid & 7;
    int hr = wy * 8 + (t >> 3), wr = wx * 8 + (t & 7);
    int h0 = (hr + SHIFT) & 63, w0 = (wr + SHIFT) & 63;
    size_t src = ((size_t)(bimg << 12) + (h0 << 6) + w0) * CDIM;

    int tid = threadIdx.x;
    float4 v = ((const float4*)(hs + src))[tid];
    float s  = v.x + v.y + v.z + v.w;
    float s2 = v.x * v.x + v.y * v.y + v.z * v.z + v.w * v.w;
#pragma unroll
    for (int o = 16; o; o >>= 1) {
        s  += __shfl_xor_sync(0xffffffffu, s,  o);
        s2 += __shfl_xor_sync(0xffffffffu, s2, o);
    }
    __shared__ float rs[4], rq[4];
    int warp = tid >> 5, lane = tid & 31;
    if (lane == 0) { rs[warp] = s; rq[warp] = s2; }
    __syncthreads();
    s  = rs[0] + rs[1] + rs[2] + rs[3];
    s2 = rq[0] + rq[1] + rq[2] + rq[3];
    float mean = s * (1.0f / 512.0f);
    float var  = s2 * (1.0f / 512.0f) - mean * mean;
    float rstd = rsqrtf(var + 1e-5f);

    int c = tid * 4;
    float4 gv = ((const float4*)g)[tid];
    float4 bv = ((const float4*)b)[tid];
    __half2* o = (__half2*)(xw + (size_t)n * CDIM + c);
    o[0] = __floats2half2_rn((v.x - mean) * rstd * gv.x + bv.x,
                             (v.y - mean) * rstd * gv.y + bv.y);
    o[1] = __floats2half2_rn((v.z - mean) * rstd * gv.z + bv.z,
                             (v.w - mean) * rstd * gv.w + bv.w);
}

// ---------------------------------------------------------------------------
// GEMM: C[M,N] = A[M,K] (fp16, row-major) * Bt[N,K]^T (fp16)
// 128x128x32 tiles, 256 threads, cp.async double buffered, mma.m16n8k16.
// EPI: 0 = +bias -> fp16 | 1 = +bias -> fp32 | 2 = gelu(+bias) -> fp16
//      3 = +bias + res -> fp32
// ---------------------------------------------------------------------------
#define BM 128
#define BN 128
#define BK 32
#define KW 40   // BK + 8 pad (halves)

template <int EPI>
__global__ __launch_bounds__(256) void gemm16(const __half* __restrict__ A,
                                              const __half* __restrict__ Bt,
                                              const float* __restrict__ bias,
                                              const float* __restrict__ res,
                                              void* __restrict__ outp,
                                              int M, int N, int K) {
    __shared__ __half sA[2][BM][KW];
    __shared__ __half sB[2][BN][KW];

    int bx = blockIdx.x, by = blockIdx.y;
    int tid = threadIdx.x;
    size_t aBase = (size_t)by * BM * K;
    size_t bBase = (size_t)bx * BN * K;

    int r0 = tid >> 2, sseg = (tid & 3) * 8;
    int r1 = r0 + 64;

    // prefetch stage 0
    {
        const __half* ag = A + aBase;
        const __half* bg = Bt + bBase;
        cp16(&sA[0][r0][sseg], ag + (size_t)r0 * K + sseg);
        cp16(&sA[0][r1][sseg], ag + (size_t)r1 * K + sseg);
        cp16(&sB[0][r0][sseg], bg + (size_t)r0 * K + sseg);
        cp16(&sB[0][r1][sseg], bg + (size_t)r1 * K + sseg);
        cp_commit();
    }

    int warp = tid >> 5, lane = tid & 31;
    int wm = warp >> 1, wn = warp & 1;   // 4 x 2 warp grid; warp tile 32 x 64

    float acc[2][8][4];
#pragma unroll
    for (int mi = 0; mi < 2; mi++)
#pragma unroll
        for (int ni = 0; ni < 8; ni++)
#pragma unroll
            for (int j = 0; j < 4; j++) acc[mi][ni][j] = 0.0f;

    int niter = K / BK;
    for (int it = 0; it < niter; ++it) {
        cp_wait0();
        __syncthreads();
        if (it + 1 < niter) {
            int ko = (it + 1) * BK;
            const __half* ag = A + aBase + ko;
            const __half* bg = Bt + bBase + ko;
            int nb = (it + 1) & 1;
            cp16(&sA[nb][r0][sseg], ag + (size_t)r0 * K + sseg);
            cp16(&sA[nb][r1][sseg], ag + (size_t)r1 * K + sseg);
            cp16(&sB[nb][r0][sseg], bg + (size_t)r0 * K + sseg);
            cp16(&sB[nb][r1][sseg], bg + (size_t)r1 * K + sseg);
        }
        cp_commit();

        int cb = it & 1;
#pragma unroll
        for (int ks = 0; ks < 2; ++ks) {
            uint32_t a[2][4];
#pragma unroll
            for (int mi = 0; mi < 2; mi++) {
                const __half* p = &sA[cb][wm * 32 + mi * 16 + (lane & 7) + ((lane >> 3) & 1) * 8]
                                     [ks * 16 + (lane >> 4) * 8];
                ldm4(a[mi][0], a[mi][1], a[mi][2], a[mi][3], p);
            }
            uint32_t bfr[8][2];
#pragma unroll
            for (int nj = 0; nj < 4; nj++) {
                const __half* p = &sB[cb][wn * 64 + nj * 16 + (lane & 7) + (lane >> 4) * 8]
                                     [ks * 16 + ((lane >> 3) & 1) * 8];
                uint32_t q0, q1, q2, q3;
                ldm4(q0, q1, q2, q3, p);
                bfr[nj * 2][0] = q0; bfr[nj * 2][1] = q1;
                bfr[nj * 2 + 1][0] = q2; bfr[nj * 2 + 1][1] = q3;
            }
#pragma unroll
            for (int mi = 0; mi < 2; mi++)
#pragma unroll
                for (int ni = 0; ni < 8; ni++)
                    mma16816(acc[mi][ni][0], acc[mi][ni][1], acc[mi][ni][2], acc[mi][ni][3],
                             a[mi][0], a[mi][1], a[mi][2], a[mi][3],
                             bfr[ni][0], bfr[ni][1]);
        }
        __syncthreads();
    }

    // epilogue
    int gm0 = by * BM + wm * 32;
    int gn0 = bx * BN + wn * 64;
#pragma unroll
    for (int mi = 0; mi < 2; mi++) {
#pragma unroll
        for (int ni = 0; ni < 8; ni++) {
            int row = gm0 + mi * 16 + (lane >> 2);
            int col = gn0 + ni * 8 + (lane & 3) * 2;
            float bv0 = bias[col], bv1 = bias[col + 1];
#pragma unroll
            for (int hf = 0; hf < 2; hf++) {
                int gr = row + hf * 8;
                float v0 = acc[mi][ni][hf * 2 + 0] + bv0;
                float v1 = acc[mi][ni][hf * 2 + 1] + bv1;
                size_t off = (size_t)gr * N + col;
                if constexpr (EPI == 0) {
                    *(__half2*)((__half*)outp + off) = __floats2half2_rn(v0, v1);
                } else if constexpr (EPI == 1) {
                    *(float2*)((float*)outp + off) = make_float2(v0, v1);
                } else if constexpr (EPI == 2) {
                    *(__half2*)((__half*)outp + off) =
                        __floats2half2_rn(gelu_tanh(v0), gelu_tanh(v1));
                } else {
                    v0 += res[off];
                    v1 += res[off + 1];
                    *(float2*)((float*)outp + off) = make_float2(v0, v1);
                }
            }
        }
    }
}

// ---------------------------------------------------------------------------
// Kernel 3: attention. One block per (window, head). 128 threads.
// ---------------------------------------------------------------------------
__global__ __launch_bounds__(128) void k_attn(const __half* __restrict__ qkv,
                                              __half* __restrict__ attn) {
    __shared__ float sq[64][36];
    __shared__ float sk[64][36];
    __shared__ float sv[64][36];
    __shared__ float sp[64][65];
    __shared__ float sinv[64];
    __shared__ int   sid[64];

    int blk = blockIdx.x;
    int w = blk >> 4, h = blk & 15;
    int tid = threadIdx.x;

    const __half* base = qkv + (size_t)w * SEQ * (3 * CDIM) + h * HEADD;
    for (int i = tid; i < SEQ * HEADD; i += 128) {
        int r = i >> 5, d = i & 31;
        const __half* p = base + (size_t)r * (3 * CDIM) + d;
        sq[r][d] = __half2float(p[0])    * 0.17677669529663687f;   // 1/sqrt(32)
        sk[r][d] = __half2float(p[512]);
        sv[r][d] = __half2float(p[1024]);
    }
    if (tid < 64) {
        int wim = w & 63;                    // window index within image
        int wy = wim >> 3, wx = wim & 7;
        int hh = wy * 8 + (tid >> 3), ww = wx * 8 + (tid & 7);
        int rh = (hh < 56) ? 0 : ((hh < 60) ? 1 : 2);
        int rw = (ww < 56) ? 0 : ((ww < 60) ? 1 : 2);
        sid[tid] = rh * 3 + rw;
    }
    __syncthreads();

    // scores: each thread does one q-row x 32 k-cols
    {
        int qr = tid >> 1, k0 = (tid & 1) * 32;
        float4 q4[8];
#pragma unroll
        for (int i = 0; i < 8; i++) q4[i] = ((const float4*)sq[qr])[i];
        int myid = sid[qr];
        for (int kk = 0; kk < 32; kk++) {
            int kr = k0 + kk;
            float s;
            if (sid[kr] != myid) {
                s = -10000.0f;
            } else {
                const float4* kp = (const float4*)sk[kr];
                s = 0.0f;
#pragma unroll
                for (int i = 0; i < 8; i++) {
                    float4 kv = kp[i];
                    s += q4[i].x * kv.x + q4[i].y * kv.y + q4[i].z * kv.z + q4[i].w * kv.w;
                }
            }
            sp[qr][kr] = s;
        }
    }
    __syncthreads();

    if (tid < 64) {
        float mx = -1e30f;
#pragma unroll 8
        for (int k = 0; k < 64; k++) mx = fmaxf(mx, sp[tid][k]);
        float sum = 0.0f;
#pragma unroll 8
        for (int k = 0; k < 64; k++) {
            float e = __expf(sp[tid][k] - mx);
            sp[tid][k] = e;
            sum += e;
        }
        sinv[tid] = 1.0f / sum;
    }
    __syncthreads();

    // P @ V: each thread does one row x 16 dims
    {
        int r = tid >> 1, d0 = (tid & 1) * 16;
        float acc[16];
#pragma unroll
        for (int j = 0; j < 16; j++) acc[j] = 0.0f;
        for (int k = 0; k < 64; k++) {
            float p = sp[r][k];
            const float4* vp = (const float4*)&sv[k][d0];
#pragma unroll
            for (int j4 = 0; j4 < 4; j4++) {
                float4 vv = vp[j4];
                acc[j4 * 4 + 0] += p * vv.x;
                acc[j4 * 4 + 1] += p * vv.y;
                acc[j4 * 4 + 2] += p * vv.z;
                acc[j4 * 4 + 3] += p * vv.w;
            }
        }
        float inv = sinv[r];
        __half2* o = (__half2*)(attn + (size_t)(w * SEQ + r) * CDIM + h * HEADD + d0);
#pragma unroll
        for (int j = 0; j < 8; j++)
            o[j] = __floats2half2_rn(acc[2 * j] * inv, acc[2 * j + 1] * inv);
    }
}

// ---------------------------------------------------------------------------
// Kernel 5: window reverse + roll(+4,+4) + residual + LN2.
// ---------------------------------------------------------------------------
__global__ __launch_bounds__(128) void k_rev_ln2(const float* __restrict__ hs,
                                                 const float* __restrict__ proj,
                                                 const float* __restrict__ g,
                                                 const float* __restrict__ b,
                                                 float* __restrict__ x,
                                                 __half* __restrict__ hout) {
    int m = blockIdx.x;
    int bimg = m >> 12;
    int hw = m & 4095;
    int h0 = hw >> 6, w0 = hw & 63;
    int hr = (h0 + 64 - SHIFT) & 63, wr = (w0 + 64 - SHIFT) & 63;
    int wy = hr >> 3, rr = hr & 7, wx = wr >> 3, cc = wr & 7;
    int n = (bimg << 12) + ((wy * 8 + wx) << 6) + (rr * 8 + cc);

    int tid = threadIdx.x;
    float4 a = ((const float4*)(hs + (size_t)m * CDIM))[tid];
    float4 p = ((const float4*)(proj + (size_t)n * CDIM))[tid];
    float4 v = make_float4(a.x + p.x, a.y + p.y, a.z + p.z, a.w + p.w);
    ((float4*)(x + (size_t)m * CDIM))[tid] = v;

    float s  = v.x + v.y + v.z + v.w;
    float s2 = v.x * v.x + v.y * v.y + v.z * v.z + v.w * v.w;
#pragma unroll
    for (int o = 16; o; o >>= 1) {
        s  += __shfl_xor_sync(0xffffffffu, s,  o);
        s2 += __shfl_xor_sync(0xffffffffu, s2, o);
    }
    __shared__ float rs[4], rq[4];
    int warp = tid >> 5, lane = tid & 31;
    if (lane == 0) { rs[warp] = s; rq[warp] = s2; }
    __syncthreads();
    s  = rs[0] + rs[1] + rs[2] + rs[3];
    s2 = rq[0] + rq[1] + rq[2] + rq[3];
    float mean = s * (1.0f / 512.0f);
    float var  = s2 * (1.0f / 512.0f) - mean * mean;
    float rstd = rsqrtf(var + 1e-5f);

    int c = tid * 4;
    float4 gv = ((const float4*)g)[tid];
    float4 bv = ((const float4*)b)[tid];
    __half2* o = (__half2*)(hout + (size_t)m * CDIM + c);
    o[0] = __floats2half2_rn((v.x - mean) * rstd * gv.x + bv.x,
                             (v.y - mean) * rstd * gv.y + bv.y);
    o[1] = __floats2half2_rn((v.z - mean) * rstd * gv.z + bv.z,
                             (v.w - mean) * rstd * gv.w + bv.w);
}

// ---------------------------------------------------------------------------
// Host launcher
// ---------------------------------------------------------------------------
extern "C" void kernel_launch(void* const* d_in, const int* in_sizes, int n_in,
                              void* d_out, int out_size) {
    const float* hs   = (const float*)d_in[0];
    const float* Wqkv = (const float*)d_in[1];
    const float* bqkv = (const float*)d_in[2];
    const float* Wo   = (const float*)d_in[3];
    const float* bo   = (const float*)d_in[4];
    const float* ln1g = (const float*)d_in[5];
    const float* ln1b = (const float*)d_in[6];
    const float* ln2g = (const float*)d_in[7];
    const float* ln2b = (const float*)d_in[8];
    const float* W1   = (const float*)d_in[9];
    const float* b1   = (const float*)d_in[10];
    const float* W2   = (const float*)d_in[11];
    const float* b2   = (const float*)d_in[12];

    __half *xw, *qkv, *attn, *hbuf, *ff, *wqkvT, *woT, *w1T, *w2T;
    float *proj, *xbuf;
    cudaGetSymbolAddress((void**)&xw,    g_xw);
    cudaGetSymbolAddress((void**)&qkv,   g_qkv);
    cudaGetSymbolAddress((void**)&attn,  g_attn);
    cudaGetSymbolAddress((void**)&proj,  g_proj);
    cudaGetSymbolAddress((void**)&xbuf,  g_x);
    cudaGetSymbolAddress((void**)&hbuf,  g_h);
    cudaGetSymbolAddress((void**)&ff,    g_ff);
    cudaGetSymbolAddress((void**)&wqkvT, g_wqkvT);
    cudaGetSymbolAddress((void**)&woT,   g_woT);
    cudaGetSymbolAddress((void**)&w1T,   g_w1T);
    cudaGetSymbolAddress((void**)&w2T,   g_w2T);

    // weight transposes (fp32 -> fp16, [K,N] -> [N,K])
    k_transpose<<<(512 * 1536 + 255) / 256, 256>>>(Wqkv, wqkvT, 512, 1536);
    k_transpose<<<(512 * 512  + 255) / 256, 256>>>(Wo,   woT,   512, 512);
    k_transpose<<<(512 * 2048 + 255) / 256, 256>>>(W1,   w1T,   512, 2048);
    k_transpose<<<(2048 * 512 + 255) / 256, 256>>>(W2,   w2T,   2048, 512);

    // 1. LN1 + shift + partition
    k_ln1<<<MTOK, 128>>>(hs, ln1g, ln1b, xw);

    // 2. QKV GEMM: [131072,512] x [512,1536]
    gemm16<0><<<dim3(1536 / BN, MTOK / BM), 256>>>(xw, wqkvT, bqkv, nullptr, qkv,
                                                   MTOK, 1536, 512);
    // 3. attention
    k_attn<<<2048 * NHEAD, 128>>>(qkv, attn);

    // 4. out projection: [131072,512] x [512,512] -> fp32
    gemm16<1><<<dim3(512 / BN, MTOK / BM), 256>>>(attn, woT, bo, nullptr, proj,
                                                  MTOK, 512, 512);
    // 5. reverse + residual + LN2
    k_rev_ln2<<<MTOK, 128>>>(hs, proj, ln2g, ln2b, xbuf, hbuf);

    // 6. MLP up + gelu: [131072,512] x [512,2048]
    gemm16<2><<<dim3(2048 / BN, MTOK / BM), 256>>>(hbuf, w1T, b1, nullptr, ff,
                                                   MTOK, 2048, 512);
    // 7. MLP down + residual -> d_out (fp32)
    gemm16<3><<<dim3(512 / BN, MTOK / BM), 256>>>(ff, w2T, b2, xbuf, d_out,
                                                  MTOK, 512, 2048);
}